// round 4
// baseline (speedup 1.0000x reference)
#include <cuda_runtime.h>

#define NMODELS 128
#define SZ      256
#define BATCH   4096
#define NTILES  4
#define TILE_O  64
#define CH      16
#define NT      128        // threads per CTA

#define XPITCH  260        // padded x row (floats) to kill 1KB-stride bank conflicts
#define W_FLOATS (SZ * TILE_O)             // 16384
#define X_FLOATS (CH * XPITCH)             // 4160
#define SMEM_BYTES ((W_FLOATS + X_FLOATS) * 4 + BATCH * 2 + 16)

typedef unsigned long long u64;

__device__ __forceinline__ u64 splat2(float x) {
    u64 r;
    asm("mov.b64 %0, {%1, %1};" : "=l"(r) : "f"(x));
    return r;
}
__device__ __forceinline__ void ffma2(u64& acc, u64 a, u64 b) {
    asm("fma.rn.f32x2 %0, %1, %2, %0;" : "+l"(acc) : "l"(a), "l"(b));
}
__device__ __forceinline__ float2 unpack2(u64 v) {
    float2 r;
    asm("mov.b64 {%0, %1}, %2;" : "=f"(r.x), "=f"(r.y) : "l"(v));
    return r;
}

__global__ void __launch_bounds__(NT, 2)
fused_kernel(const float* __restrict__ inp,
             const int*   __restrict__ ids,
             const float* __restrict__ wlut,
             const float* __restrict__ blut,
             float* __restrict__ out)
{
    extern __shared__ float smem[];
    float* w_s = smem;                               // [k][64]
    float* x_s = w_s + W_FLOATS;                     // [s][XPITCH]
    unsigned short* bucket = (unsigned short*)(x_s + X_FLOATS);
    __shared__ int cnt_s;

    const int t    = threadIdx.x;
    const int m    = blockIdx.x >> 2;
    const int tile = blockIdx.x & 3;
    const int og   = t & 7;        // output group: owns outs og*4..+3 and 32+og*4..+3
    const int sg   = t >> 3;       // sample slot 0..15

    if (t == 0) cnt_s = 0;
    __syncthreads();

    // ---- scan agent_ids -> smem bucket ----
    #pragma unroll 8
    for (int b = t; b < BATCH; b += NT) {
        if (__ldg(&ids[b]) == m) {
            int p = atomicAdd(&cnt_s, 1);
            bucket[p] = (unsigned short)b;
        }
    }

    // ---- load W tile [256][64] into smem ----
    const float* wm = wlut + (size_t)m * SZ * SZ + tile * TILE_O;
    float4* w_s4 = (float4*)w_s;
    #pragma unroll
    for (int k = t; k < W_FLOATS / 4; k += NT) {
        int i  = k >> 4;
        int j4 = k & 15;
        w_s4[k] = ((const float4*)(wm + (size_t)i * SZ))[j4];
    }

    // bias for this thread's 8 outputs
    const float* bm = blut + m * SZ + tile * TILE_O;
    float4 biasA = ((const float4*)bm)[og];          // outs og*4..+3
    float4 biasB = ((const float4*)bm)[8 + og];      // outs 32+og*4..+3

    __syncthreads();
    const int cnt = cnt_s;
    if (cnt == 0) return;

    const ulonglong2* W2 = (const ulonglong2*)w_s;   // row = 16 ulonglong2 (64 floats)

    for (int s0 = 0; s0 < cnt; s0 += CH) {
        const int ns = min(CH, cnt - s0);

        // ---- load up to CH input rows into padded x smem (zero-pad) ----
        #pragma unroll
        for (int k = t; k < CH * SZ / 4; k += NT) {
            int s  = k >> 6;
            int i4 = k & 63;
            float4 v = make_float4(0.f, 0.f, 0.f, 0.f);
            if (s < ns) v = ((const float4*)(inp + (size_t)bucket[s0 + s] * SZ))[i4];
            *(float4*)&x_s[s * XPITCH + i4 * 4] = v;
        }
        __syncthreads();

        // ---- full-K accumulation: 1 sample x 8 outputs, packed f32x2 ----
        u64 acc0 = 0, acc1 = 0, acc2 = 0, acc3 = 0;
        const float* xrow = &x_s[sg * XPITCH];

        #pragma unroll 4
        for (int k = 0; k < SZ; k += 4) {
            float4 xv = *(const float4*)&xrow[k];
            u64 xx0 = splat2(xv.x), xx1 = splat2(xv.y);
            u64 xx2 = splat2(xv.z), xx3 = splat2(xv.w);

            ulonglong2 wA0 = W2[(k + 0) * 16 + og];       // outs og*4..+3
            ulonglong2 wB0 = W2[(k + 0) * 16 + og + 8];   // outs 32+og*4..+3
            ffma2(acc0, xx0, wA0.x); ffma2(acc1, xx0, wA0.y);
            ffma2(acc2, xx0, wB0.x); ffma2(acc3, xx0, wB0.y);

            ulonglong2 wA1 = W2[(k + 1) * 16 + og];
            ulonglong2 wB1 = W2[(k + 1) * 16 + og + 8];
            ffma2(acc0, xx1, wA1.x); ffma2(acc1, xx1, wA1.y);
            ffma2(acc2, xx1, wB1.x); ffma2(acc3, xx1, wB1.y);

            ulonglong2 wA2 = W2[(k + 2) * 16 + og];
            ulonglong2 wB2 = W2[(k + 2) * 16 + og + 8];
            ffma2(acc0, xx2, wA2.x); ffma2(acc1, xx2, wA2.y);
            ffma2(acc2, xx2, wB2.x); ffma2(acc3, xx2, wB2.y);

            ulonglong2 wA3 = W2[(k + 3) * 16 + og];
            ulonglong2 wB3 = W2[(k + 3) * 16 + og + 8];
            ffma2(acc0, xx3, wA3.x); ffma2(acc1, xx3, wA3.y);
            ffma2(acc2, xx3, wB3.x); ffma2(acc3, xx3, wB3.y);
        }

        // ---- epilogue: add bias, store 8 outputs for this sample ----
        if (sg < ns) {
            float* orow = out + (size_t)bucket[s0 + sg] * SZ + tile * TILE_O;
            float2 a0 = unpack2(acc0), a1 = unpack2(acc1);
            float2 a2 = unpack2(acc2), a3 = unpack2(acc3);
            float4 rA = make_float4(a0.x + biasA.x, a0.y + biasA.y,
                                    a1.x + biasA.z, a1.y + biasA.w);
            float4 rB = make_float4(a2.x + biasB.x, a2.y + biasB.y,
                                    a3.x + biasB.z, a3.y + biasB.w);
            ((float4*)orow)[og]     = rA;
            ((float4*)orow)[8 + og] = rB;
        }
        __syncthreads();   // protect x_s before next chunk
    }
}

extern "C" void kernel_launch(void* const* d_in, const int* in_sizes, int n_in,
                              void* d_out, int out_size) {
    const float* inp  = (const float*)d_in[0];
    const int*   ids  = (const int*)  d_in[1];
    const float* wlut = (const float*)d_in[2];
    const float* blut = (const float*)d_in[3];
    float* out = (float*)d_out;

    cudaFuncSetAttribute(fused_kernel,
                         cudaFuncAttributeMaxDynamicSharedMemorySize, SMEM_BYTES);

    fused_kernel<<<NMODELS * NTILES, NT, SMEM_BYTES>>>(inp, ids, wlut, blut, out);
}

// round 5
// speedup vs baseline: 1.2048x; 1.2048x over previous
#include <cuda_runtime.h>

#define NMODELS 128
#define SZ      256
#define BATCH   4096
#define NTILES  4
#define TILE_O  64
#define NT      256
#define CH      32         // samples per chunk (16 slots x 2 samples)

#define W_FLOATS (SZ * TILE_O)                       // 16384
#define SMEM_BYTES (W_FLOATS * 4 + BATCH * 2 + 16)   // ~73.7 KB -> 3 CTAs/SM

__global__ void __launch_bounds__(NT, 3)
fused_kernel(const float* __restrict__ inp,
             const int*   __restrict__ ids,
             const float* __restrict__ wlut,
             const float* __restrict__ blut,
             float* __restrict__ out)
{
    extern __shared__ float smem[];
    float* w_s = smem;                                // [k][64]
    unsigned short* bucket = (unsigned short*)(w_s + W_FLOATS);
    __shared__ int cnt_s;

    const int t    = threadIdx.x;
    const int m    = blockIdx.x >> 2;
    const int tile = blockIdx.x & 3;
    const int og   = t & 15;       // 4 outputs: og*4 .. og*4+3
    const int sg   = t >> 4;       // sample slot 0..15 (2 samples each)

    if (t == 0) cnt_s = 0;
    __syncthreads();

    // ---- scan agent_ids -> smem bucket ----
    #pragma unroll 8
    for (int b = t; b < BATCH; b += NT) {
        if (__ldg(&ids[b]) == m) {
            int p = atomicAdd(&cnt_s, 1);
            bucket[p] = (unsigned short)b;
        }
    }

    // ---- load W tile [256][64] into smem ----
    const float* wm = wlut + (size_t)m * SZ * SZ + tile * TILE_O;
    float4* w_s4 = (float4*)w_s;
    #pragma unroll
    for (int k = t; k < W_FLOATS / 4; k += NT) {
        int i  = k >> 4;
        int j4 = k & 15;
        w_s4[k] = ((const float4*)(wm + (size_t)i * SZ))[j4];
    }

    // bias for this thread's 4 outputs
    const float4 bias = ((const float4*)(blut + m * SZ + tile * TILE_O))[og];

    __syncthreads();
    const int cnt = cnt_s;
    if (cnt == 0) return;

    for (int s0 = 0; s0 < cnt; s0 += CH) {
        const int i0 = s0 + 2 * sg;
        const int i1 = i0 + 1;
        const bool v0 = i0 < cnt;
        const bool v1 = i1 < cnt;
        const int b0 = bucket[v0 ? i0 : 0];
        const int b1 = bucket[v1 ? i1 : 0];
        const float4* x0 = (const float4*)(inp + (size_t)b0 * SZ);
        const float4* x1 = (const float4*)(inp + (size_t)b1 * SZ);

        float a00 = 0.f, a01 = 0.f, a02 = 0.f, a03 = 0.f;
        float a10 = 0.f, a11 = 0.f, a12 = 0.f, a13 = 0.f;

        #pragma unroll 8
        for (int k4 = 0; k4 < SZ / 4; k4++) {
            float4 xa = __ldg(&x0[k4]);
            float4 xb = __ldg(&x1[k4]);
            const float* wr = &w_s[(k4 * 4) * TILE_O + og * 4];

            float4 w0 = *(const float4*)(wr);
            a00 = fmaf(xa.x, w0.x, a00); a01 = fmaf(xa.x, w0.y, a01);
            a02 = fmaf(xa.x, w0.z, a02); a03 = fmaf(xa.x, w0.w, a03);
            a10 = fmaf(xb.x, w0.x, a10); a11 = fmaf(xb.x, w0.y, a11);
            a12 = fmaf(xb.x, w0.z, a12); a13 = fmaf(xb.x, w0.w, a13);

            float4 w1 = *(const float4*)(wr + TILE_O);
            a00 = fmaf(xa.y, w1.x, a00); a01 = fmaf(xa.y, w1.y, a01);
            a02 = fmaf(xa.y, w1.z, a02); a03 = fmaf(xa.y, w1.w, a03);
            a10 = fmaf(xb.y, w1.x, a10); a11 = fmaf(xb.y, w1.y, a11);
            a12 = fmaf(xb.y, w1.z, a12); a13 = fmaf(xb.y, w1.w, a13);

            float4 w2 = *(const float4*)(wr + 2 * TILE_O);
            a00 = fmaf(xa.z, w2.x, a00); a01 = fmaf(xa.z, w2.y, a01);
            a02 = fmaf(xa.z, w2.z, a02); a03 = fmaf(xa.z, w2.w, a03);
            a10 = fmaf(xb.z, w2.x, a10); a11 = fmaf(xb.z, w2.y, a11);
            a12 = fmaf(xb.z, w2.z, a12); a13 = fmaf(xb.z, w2.w, a13);

            float4 w3 = *(const float4*)(wr + 3 * TILE_O);
            a00 = fmaf(xa.w, w3.x, a00); a01 = fmaf(xa.w, w3.y, a01);
            a02 = fmaf(xa.w, w3.z, a02); a03 = fmaf(xa.w, w3.w, a03);
            a10 = fmaf(xb.w, w3.x, a10); a11 = fmaf(xb.w, w3.y, a11);
            a12 = fmaf(xb.w, w3.z, a12); a13 = fmaf(xb.w, w3.w, a13);
        }

        if (v0) {
            float4 r = make_float4(a00 + bias.x, a01 + bias.y,
                                   a02 + bias.z, a03 + bias.w);
            ((float4*)(out + (size_t)b0 * SZ + tile * TILE_O))[og] = r;
        }
        if (v1) {
            float4 r = make_float4(a10 + bias.x, a11 + bias.y,
                                   a12 + bias.z, a13 + bias.w);
            ((float4*)(out + (size_t)b1 * SZ + tile * TILE_O))[og] = r;
        }
    }
}

extern "C" void kernel_launch(void* const* d_in, const int* in_sizes, int n_in,
                              void* d_out, int out_size) {
    const float* inp  = (const float*)d_in[0];
    const int*   ids  = (const int*)  d_in[1];
    const float* wlut = (const float*)d_in[2];
    const float* blut = (const float*)d_in[3];
    float* out = (float*)d_out;

    cudaFuncSetAttribute(fused_kernel,
                         cudaFuncAttributeMaxDynamicSharedMemorySize, SMEM_BYTES);

    fused_kernel<<<NMODELS * NTILES, NT, SMEM_BYTES>>>(inp, ids, wlut, blut, out);
}

// round 6
// speedup vs baseline: 1.4055x; 1.1665x over previous
#include <cuda_runtime.h>

#define NMODELS 128
#define SZ      256
#define BATCH   4096
#define NTILES  4
#define TILE_O  64
#define NT      256
#define CH      32         // samples per chunk (16 slots x 2, striped)

#define XPITCH  260        // padded x row pitch in floats (1040B, 16B-aligned)
#define W_FLOATS (SZ * TILE_O)                    // 16384
#define X_FLOATS (CH * XPITCH)                    // 8320
#define SMEM_BYTES ((W_FLOATS + X_FLOATS) * 4 + BATCH * 2 + 16)   // ~105.5 KB

__global__ void __launch_bounds__(NT, 2)
fused_kernel(const float* __restrict__ inp,
             const int*   __restrict__ ids,
             const float* __restrict__ wlut,
             const float* __restrict__ blut,
             float* __restrict__ out)
{
    extern __shared__ float smem[];
    float* w_s = smem;                             // [k][64]
    float* x_s = w_s + W_FLOATS;                   // [s][XPITCH]
    unsigned short* bucket = (unsigned short*)(x_s + X_FLOATS);
    __shared__ int cnt_s;

    const int t    = threadIdx.x;
    const int m    = blockIdx.x >> 2;
    const int tile = blockIdx.x & 3;
    const int og   = t & 15;       // 4 outputs: og*4 .. og*4+3
    const int sg   = t >> 4;       // slot 0..15; samples s0+sg and s0+sg+16

    if (t == 0) cnt_s = 0;
    __syncthreads();

    // ---- scan agent_ids -> smem bucket ----
    #pragma unroll 8
    for (int b = t; b < BATCH; b += NT) {
        if (__ldg(&ids[b]) == m) {
            int p = atomicAdd(&cnt_s, 1);
            bucket[p] = (unsigned short)b;
        }
    }

    // ---- load W tile [256][64] into smem ----
    const float* wm = wlut + (size_t)m * SZ * SZ + tile * TILE_O;
    float4* w_s4 = (float4*)w_s;
    #pragma unroll
    for (int k = t; k < W_FLOATS / 4; k += NT) {
        int i  = k >> 4;
        int j4 = k & 15;
        w_s4[k] = ((const float4*)(wm + (size_t)i * SZ))[j4];
    }

    const float4 bias = ((const float4*)(blut + m * SZ + tile * TILE_O))[og];

    __syncthreads();
    const int cnt = cnt_s;
    if (cnt == 0) return;

    for (int s0 = 0; s0 < cnt; s0 += CH) {
        // ---- stage up to CH gathered input rows into smem (zero-pad) ----
        #pragma unroll
        for (int k = t; k < CH * SZ / 4; k += NT) {
            int s  = k >> 6;
            int i4 = k & 63;
            int idx = s0 + s;
            float4 v = make_float4(0.f, 0.f, 0.f, 0.f);
            if (idx < cnt) v = __ldg(&((const float4*)(inp + (size_t)bucket[idx] * SZ))[i4]);
            *(float4*)&x_s[s * XPITCH + i4 * 4] = v;
        }
        __syncthreads();

        const int i0 = s0 + sg;
        const int i1 = i0 + 16;
        const bool v0 = i0 < cnt;           // v0 false => v1 false (striped)
        const bool v1 = i1 < cnt;

        if (v0) {
            const float* xr0 = &x_s[sg * XPITCH];
            const float* xr1 = &x_s[(sg + 16) * XPITCH];

            float a00 = 0.f, a01 = 0.f, a02 = 0.f, a03 = 0.f;
            float a10 = 0.f, a11 = 0.f, a12 = 0.f, a13 = 0.f;

            #pragma unroll 4
            for (int k4 = 0; k4 < SZ / 4; k4++) {
                float4 xa = *(const float4*)&xr0[k4 * 4];
                float4 xb = *(const float4*)&xr1[k4 * 4];
                const float* wr = &w_s[(k4 * 4) * TILE_O + og * 4];

                float4 w0 = *(const float4*)(wr);
                a00 = fmaf(xa.x, w0.x, a00); a01 = fmaf(xa.x, w0.y, a01);
                a02 = fmaf(xa.x, w0.z, a02); a03 = fmaf(xa.x, w0.w, a03);
                a10 = fmaf(xb.x, w0.x, a10); a11 = fmaf(xb.x, w0.y, a11);
                a12 = fmaf(xb.x, w0.z, a12); a13 = fmaf(xb.x, w0.w, a13);

                float4 w1 = *(const float4*)(wr + TILE_O);
                a00 = fmaf(xa.y, w1.x, a00); a01 = fmaf(xa.y, w1.y, a01);
                a02 = fmaf(xa.y, w1.z, a02); a03 = fmaf(xa.y, w1.w, a03);
                a10 = fmaf(xb.y, w1.x, a10); a11 = fmaf(xb.y, w1.y, a11);
                a12 = fmaf(xb.y, w1.z, a12); a13 = fmaf(xb.y, w1.w, a13);

                float4 w2 = *(const float4*)(wr + 2 * TILE_O);
                a00 = fmaf(xa.z, w2.x, a00); a01 = fmaf(xa.z, w2.y, a01);
                a02 = fmaf(xa.z, w2.z, a02); a03 = fmaf(xa.z, w2.w, a03);
                a10 = fmaf(xb.z, w2.x, a10); a11 = fmaf(xb.z, w2.y, a11);
                a12 = fmaf(xb.z, w2.z, a12); a13 = fmaf(xb.z, w2.w, a13);

                float4 w3 = *(const float4*)(wr + 3 * TILE_O);
                a00 = fmaf(xa.w, w3.x, a00); a01 = fmaf(xa.w, w3.y, a01);
                a02 = fmaf(xa.w, w3.z, a02); a03 = fmaf(xa.w, w3.w, a03);
                a10 = fmaf(xb.w, w3.x, a10); a11 = fmaf(xb.w, w3.y, a11);
                a12 = fmaf(xb.w, w3.z, a12); a13 = fmaf(xb.w, w3.w, a13);
            }

            {
                float4 r = make_float4(a00 + bias.x, a01 + bias.y,
                                       a02 + bias.z, a03 + bias.w);
                ((float4*)(out + (size_t)bucket[i0] * SZ + tile * TILE_O))[og] = r;
            }
            if (v1) {
                float4 r = make_float4(a10 + bias.x, a11 + bias.y,
                                       a12 + bias.z, a13 + bias.w);
                ((float4*)(out + (size_t)bucket[i1] * SZ + tile * TILE_O))[og] = r;
            }
        }
        __syncthreads();   // protect x_s before next chunk
    }
}

extern "C" void kernel_launch(void* const* d_in, const int* in_sizes, int n_in,
                              void* d_out, int out_size) {
    const float* inp  = (const float*)d_in[0];
    const int*   ids  = (const int*)  d_in[1];
    const float* wlut = (const float*)d_in[2];
    const float* blut = (const float*)d_in[3];
    float* out = (float*)d_out;

    cudaFuncSetAttribute(fused_kernel,
                         cudaFuncAttributeMaxDynamicSharedMemorySize, SMEM_BYTES);

    fused_kernel<<<NMODELS * NTILES, NT, SMEM_BYTES>>>(inp, ids, wlut, blut, out);
}